// round 13
// baseline (speedup 1.0000x reference)
#include <cuda_runtime.h>
#include <math.h>

#define NP   128
#define DD   2048
#define NN   16384
#define NBLK 148
#define NTHR 512
#define ZSL  32      // K slices in phase A

// ---------------- scratch (no allocations allowed) ----------------
__device__ float    g_part[ZSL*NN];   // phase-A partials
__device__ float    g_dump[NBLK*NTHR];
__device__ float    g_Q[NN];          // Q = V G^T
__device__ float    g_S[NN];          // S = Q Q^T / 128 (summed, symmetric)
__device__ unsigned g_cnt[16*32];     // 16 leaf counters, 128B apart
__device__ unsigned g_root[32];
__device__ unsigned g_epoch[32];      // monotonic barrier epoch

// ---------------- shared memory union ----------------
struct SmemAll {
    union {
        struct { float4 As4[64][17]; float4 Bs4[64][17]; } a;            // 34.8 KB GEMM
        struct { float4 pc[256][4]; } r;                                  // combine (aliases a)
        struct { float pacc[4][128]; } bred;                              // phase B combine
        struct { float sd[128];
                 unsigned hist[256]; unsigned wsum[8]; unsigned sel[4]; } m;  // median
        struct { float sd[128]; float rs[8];
                 float4 Wk4[8][32];
                 float pacc[8192];                                        // 32 KB partials
                 float4 Wb4[8][32]; } e;                                  // ~40.5 KB EF
    };
};

// ---------------- acquire/release helpers ----------------
__device__ __forceinline__ unsigned ld_acq(unsigned* p) {
    unsigned v;
    asm volatile("ld.acquire.gpu.u32 %0, [%1];" : "=r"(v) : "l"(p) : "memory");
    return v;
}
__device__ __forceinline__ void st_rel(unsigned* p, unsigned v) {
    asm volatile("st.release.gpu.u32 [%0], %1;" :: "l"(p), "r"(v) : "memory");
}

// ---------------- grid barrier: 16-leaf tree, monotonic epoch ----------------
// 148 blocks: leaves 0..3 get 10 blocks, leaves 4..15 get 9.
__device__ __forceinline__ void gbar(unsigned v, int b) {
    __syncthreads();
    if (threadIdx.x == 0) {
        __threadfence();
        int leaf = b & 15;
        unsigned leafsz = (leaf < 4) ? 10u : 9u;
        unsigned r = atomicAdd(&g_cnt[leaf * 32], 1u);
        if (r == leafsz * v - 1u) {
            unsigned r2 = atomicAdd(&g_root[0], 1u);
            if (r2 == 16u * v - 1u) st_rel(&g_epoch[0], v);
        }
        while (ld_acq(&g_epoch[0]) < v) __nanosleep(16);
        __threadfence();
    }
    __syncthreads();
}

// ============================================================
// 64x64 tile of A x B^T over nch K-chunks of 64, 512 threads.
// kh = t>>8 splits each chunk's K 32+32; combine once at the end.
// ============================================================
__device__ __forceinline__ void dot64w(SmemAll* sm,
                                       const float* __restrict__ A,
                                       const float* __restrict__ B,
                                       float* __restrict__ C,
                                       int arow0, int brow0, int k0, int nch,
                                       int K, float scale)
{
    int t = threadIdx.x;
    int tx = t & 15, ty = (t >> 4) & 15, kh = t >> 8;
    const float4* A4 = (const float4*)A;
    const float4* B4 = (const float4*)B;
    int K4 = K >> 2;
    float* Asf = (float*)&sm->a.As4[0][0];   // row stride 68 floats
    float* Bsf = (float*)&sm->a.Bs4[0][0];

    float acc[4][4];
    #pragma unroll
    for (int i = 0; i < 4; i++)
        #pragma unroll
        for (int j = 0; j < 4; j++) acc[i][j] = 0.f;

    for (int ch = 0; ch < nch; ch++) {
        int q0 = (k0 >> 2) + ch * 16;
        __syncthreads();
        #pragma unroll
        for (int p = 0; p < 4; p++) {
            int idx = t + p * 512;                  // 0..2047
            int mat = idx >> 10;                    // 0=A, 1=B
            int rr = (idx >> 4) & 63, q = idx & 15;
            const float4* S4 = mat ? B4 : A4;
            float* D = mat ? Bsf : Asf;
            int row0 = mat ? brow0 : arow0;
            float4 v = S4[(row0 + rr) * K4 + q0 + q];
            int cp = (((rr >> 2) ^ q) << 2) | (rr & 3);
            int kb = 4 * q;
            D[(kb    ) * 68 + cp] = v.x;
            D[(kb + 1) * 68 + cp] = v.y;
            D[(kb + 2) * 68 + cp] = v.z;
            D[(kb + 3) * 68 + cp] = v.w;
        }
        __syncthreads();
        int kb0 = kh * 32;
        #pragma unroll 8
        for (int k = kb0; k < kb0 + 32; k++) {
            int s = k >> 2;
            float4 av = sm->a.As4[k][ty ^ s];
            float4 bv = sm->a.Bs4[k][tx ^ s];
            acc[0][0] += av.x*bv.x; acc[0][1] += av.x*bv.y; acc[0][2] += av.x*bv.z; acc[0][3] += av.x*bv.w;
            acc[1][0] += av.y*bv.x; acc[1][1] += av.y*bv.y; acc[1][2] += av.y*bv.z; acc[1][3] += av.y*bv.w;
            acc[2][0] += av.z*bv.x; acc[2][1] += av.z*bv.y; acc[2][2] += av.z*bv.z; acc[2][3] += av.z*bv.w;
            acc[3][0] += av.w*bv.x; acc[3][1] += av.w*bv.y; acc[3][2] += av.w*bv.z; acc[3][3] += av.w*bv.w;
        }
    }
    __syncthreads();                            // done reading As/Bs (pc aliases)
    int slot = ty * 16 + tx;
    if (kh == 1) {
        #pragma unroll
        for (int i = 0; i < 4; i++)
            sm->r.pc[slot][i] = make_float4(acc[i][0], acc[i][1], acc[i][2], acc[i][3]);
    }
    __syncthreads();
    if (kh == 0) {
        #pragma unroll
        for (int i = 0; i < 4; i++) {
            float4 o = sm->r.pc[slot][i];
            o.x = (o.x + acc[i][0]) * scale;
            o.y = (o.y + acc[i][1]) * scale;
            o.z = (o.z + acc[i][2]) * scale;
            o.w = (o.w + acc[i][3]) * scale;
            *(float4*)&C[(arow0 + 4*ty + i) * NP + brow0 + 4*tx] = o;
        }
    }
}

__device__ __forceinline__ unsigned f2key(float d) {
    unsigned u = __float_as_uint(d);
    return (u & 0x80000000u) ? ~u : (u | 0x80000000u);
}

#define KSENT 0xFFFFFFFFu
#define ZKEY  0x80000000u   // f2key(0.0f)

// ==================================================================
__global__ void __launch_bounds__(NTHR, 1)
stein_fused(const float* __restrict__ V, const float* __restrict__ G,
            float* __restrict__ out)
{
    __shared__ SmemAll sm;
    int b = blockIdx.x, t = threadIdx.x;
    int lane = t & 31, wid = t >> 5;
    unsigned base = ld_acq(&g_epoch[0]);   // settled epoch from previous launch

    // ---- Phase A: Q partials, 4 tiles x 32 K-slices of 64 (blocks 0..127) ----
    if (b < 128) {
        int tile = b & 3, z = b >> 2;
        dot64w(&sm, V, G, g_part + z * NN, (tile >> 1) * 64, (tile & 1) * 64,
               z * 64, 1, DD, 1.0f);
    }
    gbar(base + 1, b);

    // ---- Phase B: reduce 32 partials -> Q (blocks 0..127, 128 elems each) ----
    if (b < 128) {
        int e0 = b * 128 + (t & 127);
        int qy = t >> 7;                       // quarter 0..3
        float s = 0.f;
        #pragma unroll
        for (int z = 0; z < 8; z++) s += g_part[(qy * 8 + z) * NN + e0];
        sm.bred.pacc[qy][t & 127] = s;
        __syncthreads();
        if (t < 128)
            g_Q[b * 128 + t] = sm.bred.pacc[0][t] + sm.bred.pacc[1][t]
                             + sm.bred.pacc[2][t] + sm.bred.pacc[3][t];
    }
    gbar(base + 2, b);

    // ---- Phase C: S = Q Q^T / 128, full K (blocks 0..3); others prewarm L1 ----
    if (b < 4) {
        dot64w(&sm, g_Q, g_Q, g_S, (b >> 1) * 64, (b & 1) * 64,
               0, 2, NP, 1.0f / 128.0f);
    } else if (b < 128) {
        // warm L1 with this block's EF working set (G column slice + Q)
        float acc = 0.f;
        if (t < 256) {
            int c2 = (b & 7) * 256 + t;
            #pragma unroll 8
            for (int j = 0; j < 128; j++) acc += G[j * DD + c2];
        } else {
            int c = t & 127;
            #pragma unroll 8
            for (int j = 0; j < 128; j++) acc += g_Q[j * NP + c];
        }
        g_dump[b * NTHR + t] = acc;            // keep loads alive (dead data)
    }
    gbar(base + 3, b);

    if (b >= 128) return;   // barrier-only blocks exit

    // ========== Phase M (replicated; symmetric; 2-pass radix, mid-bucket) ==========
    if (t < 128) sm.m.sd[t] = g_S[t * NP + t];
    __syncthreads();

    unsigned keys[32];
    {
        int i = t >> 2, j0q = (t & 3) * 32;
        float sdi = sm.m.sd[i];
        const float4* S4p = (const float4*)(g_S + i * NP + j0q);
        #pragma unroll
        for (int e4 = 0; e4 < 8; e4++) {
            int j = j0q + 4 * e4;
            if (j + 3 > i) {
                float4 s4 = S4p[e4];
                keys[4*e4+0] = (j+0 > i) ? f2key((sdi + sm.m.sd[j+0]) - (s4.x + s4.x)) : KSENT;
                keys[4*e4+1] = (j+1 > i) ? f2key((sdi + sm.m.sd[j+1]) - (s4.y + s4.y)) : KSENT;
                keys[4*e4+2] = (j+2 > i) ? f2key((sdi + sm.m.sd[j+2]) - (s4.z + s4.z)) : KSENT;
                keys[4*e4+3] = (j+3 > i) ? f2key((sdi + sm.m.sd[j+3]) - (s4.w + s4.w)) : KSENT;
            } else {
                keys[4*e4+0] = KSENT; keys[4*e4+1] = KSENT;
                keys[4*e4+2] = KSENT; keys[4*e4+3] = KSENT;
            }
        }
    }

    unsigned hi_mask = 0u, hi_val = 0u, krank = 8192u;
    #pragma unroll
    for (int p = 0; p < 2; p++) {
        int shift = 24 - 8 * p;
        if (t < 256) sm.m.hist[t] = 0u;
        __syncthreads();
        if (p == 0) {
            // all keys active: warp-aggregate, weight 2 each; sentinels land in bin 255
            #pragma unroll
            for (int e = 0; e < 32; e++) {
                unsigned bin = keys[e] >> 24;
                unsigned mm = __match_any_sync(0xFFFFFFFFu, bin);
                if ((int)(__ffs(mm) - 1) == lane)
                    atomicAdd(&sm.m.hist[bin], 2u * (unsigned)__popc(mm));
            }
            if (t == 0) atomicAdd(&sm.m.hist[ZKEY >> 24], 128u);   // diag zeros
        } else {
            #pragma unroll
            for (int e = 0; e < 32; e++) {
                unsigned key = keys[e];
                if ((key & hi_mask) == hi_val)
                    atomicAdd(&sm.m.hist[(key >> shift) & 255u], 2u);
            }
            if (t == 0 && (ZKEY & hi_mask) == hi_val)
                atomicAdd(&sm.m.hist[(ZKEY >> shift) & 255u], 128u);
        }
        __syncthreads();
        unsigned v = 0, incl = 0;
        if (t < 256) {
            v = sm.m.hist[t]; incl = v;
            #pragma unroll
            for (int off = 1; off < 32; off <<= 1) {
                unsigned nv = __shfl_up_sync(0xFFFFFFFFu, incl, off);
                if (lane >= off) incl += nv;
            }
            if (lane == 31) sm.m.wsum[wid] = incl;
        }
        __syncthreads();
        if (t < 8) {
            unsigned w = sm.m.wsum[t], in2 = w;
            #pragma unroll
            for (int off = 1; off < 8; off <<= 1) {
                unsigned nv = __shfl_up_sync(0xFFu, in2, off);
                if (t >= off) in2 += nv;
            }
            sm.m.wsum[t] = in2 - w;
        }
        __syncthreads();
        if (t < 256) {
            unsigned excl = incl - v + sm.m.wsum[wid];
            if (excl <= krank && krank < excl + v) {
                sm.m.sel[0] = (unsigned)t;
                sm.m.sel[1] = krank - excl;
            }
        }
        __syncthreads();
        hi_mask |= (0xFFu << shift);
        hi_val  |= (sm.m.sel[0] << shift);
        krank    = sm.m.sel[1];
        __syncthreads();
    }
    // mid-bucket key: h is ~1e4x larger than dMsd, so 0.2% med error is harmless
    unsigned medkey = hi_val | 0x8000u;

    float inv2h, invh128;
    {
        unsigned u = (medkey & 0x80000000u) ? (medkey ^ 0x80000000u) : ~medkey;
        float med = __uint_as_float(u);
        float h = (med * med) / 6.9314718f;   // ln(128)
        inv2h = 0.5f / h;
        invh128 = 1.0f / (h * 128.0f);
    }
    __syncthreads();    // m -> e union switch (sd at same offset, preserved)

    // ================= Phase EF =================
    {
        int r0 = (b >> 3) * 8, cg = b & 7;
        float* Wk = (float*)&sm.e.Wk4[0][0];
        float* Wb = (float*)&sm.e.Wb4[0][0];

        // kern rows r0..r0+7 (2 per thread)
        #pragma unroll
        for (int p = 0; p < 2; p++) {
            int idx = t + p * 512;
            int r = idx >> 7, j = idx & 127;
            int i = r0 + r;
            float s = g_S[i * NP + j];
            float d = (sm.e.sd[i] + sm.e.sd[j]) - (s + s);
            Wk[r * 128 + j] = __expf(-d * inv2h);
        }
        __syncthreads();

        // rowsums: warps 0..7 reduce rows 0..7
        if (wid < 8) {
            float v = Wk[wid*128 + lane] + Wk[wid*128 + lane + 32]
                    + Wk[wid*128 + lane + 64] + Wk[wid*128 + lane + 96];
            #pragma unroll
            for (int off = 16; off > 0; off >>= 1)
                v += __shfl_down_sync(0xFFFFFFFFu, v, off);
            if (lane == 0) sm.e.rs[wid] = v;
        }
        __syncthreads();

        // kern @ Q : vectorized. thread = (colpair 0..63, jchunk 0..7 of 16)
        {
            int cpair = t & 63, chunk = t >> 6;
            const float2* Q2 = (const float2*)g_Q;    // row stride 64 float2
            float2 acc[8];
            #pragma unroll
            for (int r = 0; r < 8; r++) acc[r] = make_float2(0.f, 0.f);
            #pragma unroll
            for (int jb = 0; jb < 4; jb++) {
                int j = chunk * 16 + jb * 4;
                float4 wv[8];
                #pragma unroll
                for (int r = 0; r < 8; r++) wv[r] = sm.e.Wk4[r][j >> 2];
                #pragma unroll
                for (int dj = 0; dj < 4; dj++) {
                    float2 q2 = Q2[(j + dj) * 64 + cpair];
                    #pragma unroll
                    for (int r = 0; r < 8; r++) {
                        float w = (dj == 0) ? wv[r].x : (dj == 1) ? wv[r].y
                                : (dj == 2) ? wv[r].z : wv[r].w;
                        acc[r].x += w * q2.x;
                        acc[r].y += w * q2.y;
                    }
                }
            }
            float2* pQ = (float2*)sm.e.pacc;          // [8 chunks][8 r][64 cpair]
            #pragma unroll
            for (int r = 0; r < 8; r++) pQ[(chunk * 8 + r) * 64 + cpair] = acc[r];
        }
        __syncthreads();

        // combine into Wb (2 entries per thread)
        #pragma unroll
        for (int p = 0; p < 2; p++) {
            int idx = t + p * 512;
            int r = idx >> 7, c = idx & 127;
            int i = r0 + r;
            float a = 0.f;
            #pragma unroll
            for (int ch = 0; ch < 8; ch++) a += sm.e.pacc[(ch * 8 + r) * 128 + c];
            Wb[r * 128 + c] = Wk[r * 128 + c]
                            + invh128 * (a - sm.e.rs[r] * g_Q[i * NP + c]);
        }
        __syncthreads();

        // out GEMM: vectorized. thread = (colpair 0..127, jchunk 0..3 of 32)
        {
            int cpair = t & 127, chunk = t >> 7;
            const float2* G2 = (const float2*)G;      // row stride 1024 float2
            int gcol = cg * 128 + cpair;
            float2 acc[8];
            #pragma unroll
            for (int r = 0; r < 8; r++) acc[r] = make_float2(0.f, 0.f);
            #pragma unroll
            for (int jb = 0; jb < 8; jb++) {
                int j = chunk * 32 + jb * 4;
                float4 wv[8];
                #pragma unroll
                for (int r = 0; r < 8; r++) wv[r] = sm.e.Wb4[r][j >> 2];
                #pragma unroll
                for (int dj = 0; dj < 4; dj++) {
                    float2 g2 = G2[(j + dj) * 1024 + gcol];
                    #pragma unroll
                    for (int r = 0; r < 8; r++) {
                        float w = (dj == 0) ? wv[r].x : (dj == 1) ? wv[r].y
                                : (dj == 2) ? wv[r].z : wv[r].w;
                        acc[r].x += w * g2.x;
                        acc[r].y += w * g2.y;
                    }
                }
            }
            float2* pO = (float2*)sm.e.pacc;          // [4 chunks][8 r][128 cpair]
            #pragma unroll
            for (int r = 0; r < 8; r++) pO[(chunk * 8 + r) * 128 + cpair] = acc[r];
        }
        __syncthreads();

        // combine + store: 4 outputs per thread
        #pragma unroll
        for (int p = 0; p < 4; p++) {
            int idx = t + p * 512;
            int r = idx >> 8, c = idx & 255;
            float v = sm.e.pacc[ r       * 256 + c] + sm.e.pacc[( 8 + r) * 256 + c]
                    + sm.e.pacc[(16 + r) * 256 + c] + sm.e.pacc[(24 + r) * 256 + c];
            out[(r0 + r) * DD + cg * 256 + c] = v;
        }
    }
}

extern "C" void kernel_launch(void* const* d_in, const int* in_sizes, int n_in,
                              void* d_out, int out_size)
{
    const float* var  = (const float*)d_in[0];
    const float* grad = (const float*)d_in[1];
    float* out = (float*)d_out;
    stein_fused<<<NBLK, NTHR>>>(var, grad, out);
}

// round 14
// speedup vs baseline: 1.0009x; 1.0009x over previous
#include <cuda_runtime.h>
#include <math.h>

#define NP   128
#define DD   2048
#define NN   16384
#define NBLK 148
#define NTHR 512
#define ZSL  32      // K slices in phase A

// ---------------- scratch (no allocations allowed) ----------------
__device__ float    g_part[ZSL*NN];   // phase-A partials
__device__ float    g_dump[NBLK*NTHR];
__device__ float    g_Q[NN];          // Q = V G^T
__device__ float    g_S[NN];          // S = Q Q^T / 128 (summed, symmetric)
__device__ unsigned g_cnt[16*32];     // 16 leaf counters, 128B apart
__device__ unsigned g_root[32];
__device__ unsigned g_epoch[32];      // monotonic barrier epoch

// ---------------- shared memory union ----------------
struct SmemAll {
    union {
        struct { float4 As4[64][17]; float4 Bs4[64][17]; } a;            // 34.8 KB GEMM
        struct { float4 pc[256][4]; } r;                                  // combine (aliases a)
        struct { float pacc[4][128]; } bred;                              // phase B combine
        struct { float sd[128];
                 unsigned hist[256]; unsigned wsum[8]; unsigned sel[4]; } m;  // median
        struct { float sd[128]; float rs[8];
                 float4 Wk4[8][32];
                 float pacc[8192];                                        // 32 KB partials
                 float4 Wb4[8][32]; } e;                                  // ~40.5 KB EF
    };
};

// ---------------- acquire/release helpers ----------------
__device__ __forceinline__ unsigned ld_acq(unsigned* p) {
    unsigned v;
    asm volatile("ld.acquire.gpu.u32 %0, [%1];" : "=r"(v) : "l"(p) : "memory");
    return v;
}
__device__ __forceinline__ void st_rel(unsigned* p, unsigned v) {
    asm volatile("st.release.gpu.u32 [%0], %1;" :: "l"(p), "r"(v) : "memory");
}

// ---------------- grid barrier: 16-leaf tree, monotonic epoch ----------------
// 148 blocks: leaves 0..3 get 10 blocks, leaves 4..15 get 9.
__device__ __forceinline__ void gbar(unsigned v, int b) {
    __syncthreads();
    if (threadIdx.x == 0) {
        __threadfence();
        int leaf = b & 15;
        unsigned leafsz = (leaf < 4) ? 10u : 9u;
        unsigned r = atomicAdd(&g_cnt[leaf * 32], 1u);
        if (r == leafsz * v - 1u) {
            unsigned r2 = atomicAdd(&g_root[0], 1u);
            if (r2 == 16u * v - 1u) st_rel(&g_epoch[0], v);
        }
        int spins = 0;
        while (ld_acq(&g_epoch[0]) < v) {
            if (++spins > 4) __nanosleep(32);
        }
        __threadfence();
    }
    __syncthreads();
}

// ============================================================
// 64x64 tile of A x B^T over nch K-chunks of 64, 512 threads.
// kh = t>>8 splits each chunk's K 32+32; combine once at the end.
// ============================================================
__device__ __forceinline__ void dot64w(SmemAll* sm,
                                       const float* __restrict__ A,
                                       const float* __restrict__ B,
                                       float* __restrict__ C,
                                       int arow0, int brow0, int k0, int nch,
                                       int K, float scale)
{
    int t = threadIdx.x;
    int tx = t & 15, ty = (t >> 4) & 15, kh = t >> 8;
    const float4* A4 = (const float4*)A;
    const float4* B4 = (const float4*)B;
    int K4 = K >> 2;
    float* Asf = (float*)&sm->a.As4[0][0];   // row stride 68 floats
    float* Bsf = (float*)&sm->a.Bs4[0][0];

    float acc[4][4];
    #pragma unroll
    for (int i = 0; i < 4; i++)
        #pragma unroll
        for (int j = 0; j < 4; j++) acc[i][j] = 0.f;

    for (int ch = 0; ch < nch; ch++) {
        int q0 = (k0 >> 2) + ch * 16;
        __syncthreads();
        #pragma unroll
        for (int p = 0; p < 4; p++) {
            int idx = t + p * 512;                  // 0..2047
            int mat = idx >> 10;                    // 0=A, 1=B
            int rr = (idx >> 4) & 63, q = idx & 15;
            const float4* S4 = mat ? B4 : A4;
            float* D = mat ? Bsf : Asf;
            int row0 = mat ? brow0 : arow0;
            float4 v = S4[(row0 + rr) * K4 + q0 + q];
            int cp = (((rr >> 2) ^ q) << 2) | (rr & 3);
            int kb = 4 * q;
            D[(kb    ) * 68 + cp] = v.x;
            D[(kb + 1) * 68 + cp] = v.y;
            D[(kb + 2) * 68 + cp] = v.z;
            D[(kb + 3) * 68 + cp] = v.w;
        }
        __syncthreads();
        int kb0 = kh * 32;
        #pragma unroll 8
        for (int k = kb0; k < kb0 + 32; k++) {
            int s = k >> 2;
            float4 av = sm->a.As4[k][ty ^ s];
            float4 bv = sm->a.Bs4[k][tx ^ s];
            acc[0][0] += av.x*bv.x; acc[0][1] += av.x*bv.y; acc[0][2] += av.x*bv.z; acc[0][3] += av.x*bv.w;
            acc[1][0] += av.y*bv.x; acc[1][1] += av.y*bv.y; acc[1][2] += av.y*bv.z; acc[1][3] += av.y*bv.w;
            acc[2][0] += av.z*bv.x; acc[2][1] += av.z*bv.y; acc[2][2] += av.z*bv.z; acc[2][3] += av.z*bv.w;
            acc[3][0] += av.w*bv.x; acc[3][1] += av.w*bv.y; acc[3][2] += av.w*bv.z; acc[3][3] += av.w*bv.w;
        }
    }
    __syncthreads();                            // done reading As/Bs (pc aliases)
    int slot = ty * 16 + tx;
    if (kh == 1) {
        #pragma unroll
        for (int i = 0; i < 4; i++)
            sm->r.pc[slot][i] = make_float4(acc[i][0], acc[i][1], acc[i][2], acc[i][3]);
    }
    __syncthreads();
    if (kh == 0) {
        #pragma unroll
        for (int i = 0; i < 4; i++) {
            float4 o = sm->r.pc[slot][i];
            o.x = (o.x + acc[i][0]) * scale;
            o.y = (o.y + acc[i][1]) * scale;
            o.z = (o.z + acc[i][2]) * scale;
            o.w = (o.w + acc[i][3]) * scale;
            *(float4*)&C[(arow0 + 4*ty + i) * NP + brow0 + 4*tx] = o;
        }
    }
}

__device__ __forceinline__ unsigned f2key(float d) {
    unsigned u = __float_as_uint(d);
    return (u & 0x80000000u) ? ~u : (u | 0x80000000u);
}

#define KSENT 0xFFFFFFFFu
#define ZKEY  0x80000000u   // f2key(0.0f)

// ==================================================================
__global__ void __launch_bounds__(NTHR, 1)
stein_fused(const float* __restrict__ V, const float* __restrict__ G,
            float* __restrict__ out)
{
    __shared__ SmemAll sm;
    int b = blockIdx.x, t = threadIdx.x;
    int lane = t & 31, wid = t >> 5;
    unsigned base = ld_acq(&g_epoch[0]);   // settled epoch from previous launch

    // ---- Phase A: Q partials, 4 tiles x 32 K-slices of 64 (blocks 0..127) ----
    if (b < 128) {
        int tile = b & 3, z = b >> 2;
        dot64w(&sm, V, G, g_part + z * NN, (tile >> 1) * 64, (tile & 1) * 64,
               z * 64, 1, DD, 1.0f);
    }
    gbar(base + 1, b);

    // ---- Phase B: reduce 32 partials -> Q (blocks 0..127, 128 elems each) ----
    if (b < 128) {
        int e0 = b * 128 + (t & 127);
        int qy = t >> 7;                       // quarter 0..3
        float s = 0.f;
        #pragma unroll
        for (int z = 0; z < 8; z++) s += g_part[(qy * 8 + z) * NN + e0];
        sm.bred.pacc[qy][t & 127] = s;
        __syncthreads();
        if (t < 128)
            g_Q[b * 128 + t] = sm.bred.pacc[0][t] + sm.bred.pacc[1][t]
                             + sm.bred.pacc[2][t] + sm.bred.pacc[3][t];
    }
    gbar(base + 2, b);

    // ---- Phase C: S = Q Q^T / 128, full K (blocks 0..3); others prewarm L1 ----
    if (b < 4) {
        dot64w(&sm, g_Q, g_Q, g_S, (b >> 1) * 64, (b & 1) * 64,
               0, 2, NP, 1.0f / 128.0f);
    } else if (b < 128) {
        // warm L1 with this block's EF working set, vectorized hi-MLP:
        // G col-slice (128 rows x 256 cols) + full Q, 24 independent LDG.128
        const float4* G4 = (const float4*)G;     // row stride 512 float4
        const float4* Q4 = (const float4*)g_Q;   // 4096 float4
        int cg4 = (b & 7) * 64;                  // slice start in float4
        float4 s = make_float4(0.f, 0.f, 0.f, 0.f);
        #pragma unroll
        for (int p = 0; p < 16; p++) {
            int idx = t + p * 512;               // 0..8191
            int row = idx >> 6, c4 = idx & 63;
            float4 v = G4[row * 512 + cg4 + c4];
            s.x += v.x; s.y += v.y; s.z += v.z; s.w += v.w;
        }
        #pragma unroll
        for (int p = 0; p < 8; p++) {
            float4 v = Q4[t + p * 512];
            s.x += v.x; s.y += v.y; s.z += v.z; s.w += v.w;
        }
        g_dump[b * NTHR + t] = s.x + s.y + s.z + s.w;   // keep loads alive
    }
    gbar(base + 3, b);

    if (b >= 128) return;   // barrier-only blocks exit

    // ========== Phase M (replicated; symmetric; 2-pass radix, mid-bucket) ==========
    if (t < 128) sm.m.sd[t] = g_S[t * NP + t];
    __syncthreads();

    unsigned keys[32];
    {
        int i = t >> 2, j0q = (t & 3) * 32;
        float sdi = sm.m.sd[i];
        const float4* S4p = (const float4*)(g_S + i * NP + j0q);
        #pragma unroll
        for (int e4 = 0; e4 < 8; e4++) {
            int j = j0q + 4 * e4;
            if (j + 3 > i) {
                float4 s4 = S4p[e4];
                keys[4*e4+0] = (j+0 > i) ? f2key((sdi + sm.m.sd[j+0]) - (s4.x + s4.x)) : KSENT;
                keys[4*e4+1] = (j+1 > i) ? f2key((sdi + sm.m.sd[j+1]) - (s4.y + s4.y)) : KSENT;
                keys[4*e4+2] = (j+2 > i) ? f2key((sdi + sm.m.sd[j+2]) - (s4.z + s4.z)) : KSENT;
                keys[4*e4+3] = (j+3 > i) ? f2key((sdi + sm.m.sd[j+3]) - (s4.w + s4.w)) : KSENT;
            } else {
                keys[4*e4+0] = KSENT; keys[4*e4+1] = KSENT;
                keys[4*e4+2] = KSENT; keys[4*e4+3] = KSENT;
            }
        }
    }

    unsigned hi_mask = 0u, hi_val = 0u, krank = 8192u;
    #pragma unroll
    for (int p = 0; p < 2; p++) {
        int shift = 24 - 8 * p;
        if (t < 256) sm.m.hist[t] = 0u;
        __syncthreads();
        if (p == 0) {
            // all keys active: warp-aggregate, weight 2 each; sentinels land in bin 255
            #pragma unroll
            for (int e = 0; e < 32; e++) {
                unsigned bin = keys[e] >> 24;
                unsigned mm = __match_any_sync(0xFFFFFFFFu, bin);
                if ((int)(__ffs(mm) - 1) == lane)
                    atomicAdd(&sm.m.hist[bin], 2u * (unsigned)__popc(mm));
            }
            if (t == 0) atomicAdd(&sm.m.hist[ZKEY >> 24], 128u);   // diag zeros
        } else {
            #pragma unroll
            for (int e = 0; e < 32; e++) {
                unsigned key = keys[e];
                if ((key & hi_mask) == hi_val)
                    atomicAdd(&sm.m.hist[(key >> shift) & 255u], 2u);
            }
            if (t == 0 && (ZKEY & hi_mask) == hi_val)
                atomicAdd(&sm.m.hist[(ZKEY >> shift) & 255u], 128u);
        }
        __syncthreads();
        unsigned v = 0, incl = 0;
        if (t < 256) {
            v = sm.m.hist[t]; incl = v;
            #pragma unroll
            for (int off = 1; off < 32; off <<= 1) {
                unsigned nv = __shfl_up_sync(0xFFFFFFFFu, incl, off);
                if (lane >= off) incl += nv;
            }
            if (lane == 31) sm.m.wsum[wid] = incl;
        }
        __syncthreads();
        if (t < 8) {
            unsigned w = sm.m.wsum[t], in2 = w;
            #pragma unroll
            for (int off = 1; off < 8; off <<= 1) {
                unsigned nv = __shfl_up_sync(0xFFu, in2, off);
                if (t >= off) in2 += nv;
            }
            sm.m.wsum[t] = in2 - w;
        }
        __syncthreads();
        if (t < 256) {
            unsigned excl = incl - v + sm.m.wsum[wid];
            if (excl <= krank && krank < excl + v) {
                sm.m.sel[0] = (unsigned)t;
                sm.m.sel[1] = krank - excl;
            }
        }
        __syncthreads();
        hi_mask |= (0xFFu << shift);
        hi_val  |= (sm.m.sel[0] << shift);
        krank    = sm.m.sel[1];
        __syncthreads();
    }
    // mid-bucket key: h is ~1e4x larger than dMsd, so 0.2% med error is harmless
    unsigned medkey = hi_val | 0x8000u;

    float inv2h, invh128;
    {
        unsigned u = (medkey & 0x80000000u) ? (medkey ^ 0x80000000u) : ~medkey;
        float med = __uint_as_float(u);
        float h = (med * med) / 6.9314718f;   // ln(128)
        inv2h = 0.5f / h;
        invh128 = 1.0f / (h * 128.0f);
    }
    __syncthreads();    // m -> e union switch (sd at same offset, preserved)

    // ================= Phase EF =================
    {
        int r0 = (b >> 3) * 8, cg = b & 7;
        float* Wk = (float*)&sm.e.Wk4[0][0];
        float* Wb = (float*)&sm.e.Wb4[0][0];

        // kern rows r0..r0+7 (2 per thread)
        #pragma unroll
        for (int p = 0; p < 2; p++) {
            int idx = t + p * 512;
            int r = idx >> 7, j = idx & 127;
            int i = r0 + r;
            float s = g_S[i * NP + j];
            float d = (sm.e.sd[i] + sm.e.sd[j]) - (s + s);
            Wk[r * 128 + j] = __expf(-d * inv2h);
        }
        __syncthreads();

        // rowsums: warps 0..7 reduce rows 0..7
        if (wid < 8) {
            float v = Wk[wid*128 + lane] + Wk[wid*128 + lane + 32]
                    + Wk[wid*128 + lane + 64] + Wk[wid*128 + lane + 96];
            #pragma unroll
            for (int off = 16; off > 0; off >>= 1)
                v += __shfl_down_sync(0xFFFFFFFFu, v, off);
            if (lane == 0) sm.e.rs[wid] = v;
        }
        __syncthreads();

        // kern @ Q : vectorized. thread = (colpair 0..63, jchunk 0..7 of 16)
        {
            int cpair = t & 63, chunk = t >> 6;
            const float2* Q2 = (const float2*)g_Q;    // row stride 64 float2
            float2 acc[8];
            #pragma unroll
            for (int r = 0; r < 8; r++) acc[r] = make_float2(0.f, 0.f);
            #pragma unroll
            for (int jb = 0; jb < 4; jb++) {
                int j = chunk * 16 + jb * 4;
                float4 wv[8];
                #pragma unroll
                for (int r = 0; r < 8; r++) wv[r] = sm.e.Wk4[r][j >> 2];
                #pragma unroll
                for (int dj = 0; dj < 4; dj++) {
                    float2 q2 = Q2[(j + dj) * 64 + cpair];
                    #pragma unroll
                    for (int r = 0; r < 8; r++) {
                        float w = (dj == 0) ? wv[r].x : (dj == 1) ? wv[r].y
                                : (dj == 2) ? wv[r].z : wv[r].w;
                        acc[r].x += w * q2.x;
                        acc[r].y += w * q2.y;
                    }
                }
            }
            float2* pQ = (float2*)sm.e.pacc;          // [8 chunks][8 r][64 cpair]
            #pragma unroll
            for (int r = 0; r < 8; r++) pQ[(chunk * 8 + r) * 64 + cpair] = acc[r];
        }
        __syncthreads();

        // combine into Wb (2 entries per thread)
        #pragma unroll
        for (int p = 0; p < 2; p++) {
            int idx = t + p * 512;
            int r = idx >> 7, c = idx & 127;
            int i = r0 + r;
            float a = 0.f;
            #pragma unroll
            for (int ch = 0; ch < 8; ch++) a += sm.e.pacc[(ch * 8 + r) * 128 + c];
            Wb[r * 128 + c] = Wk[r * 128 + c]
                            + invh128 * (a - sm.e.rs[r] * g_Q[i * NP + c]);
        }
        __syncthreads();

        // out GEMM: vectorized. thread = (colpair 0..127, jchunk 0..3 of 32)
        {
            int cpair = t & 127, chunk = t >> 7;
            const float2* G2 = (const float2*)G;      // row stride 1024 float2
            int gcol = cg * 128 + cpair;
            float2 acc[8];
            #pragma unroll
            for (int r = 0; r < 8; r++) acc[r] = make_float2(0.f, 0.f);
            #pragma unroll
            for (int jb = 0; jb < 8; jb++) {
                int j = chunk * 32 + jb * 4;
                float4 wv[8];
                #pragma unroll
                for (int r = 0; r < 8; r++) wv[r] = sm.e.Wb4[r][j >> 2];
                #pragma unroll
                for (int dj = 0; dj < 4; dj++) {
                    float2 g2 = G2[(j + dj) * 1024 + gcol];
                    #pragma unroll
                    for (int r = 0; r < 8; r++) {
                        float w = (dj == 0) ? wv[r].x : (dj == 1) ? wv[r].y
                                : (dj == 2) ? wv[r].z : wv[r].w;
                        acc[r].x += w * g2.x;
                        acc[r].y += w * g2.y;
                    }
                }
            }
            float2* pO = (float2*)sm.e.pacc;          // [4 chunks][8 r][128 cpair]
            #pragma unroll
            for (int r = 0; r < 8; r++) pO[(chunk * 8 + r) * 128 + cpair] = acc[r];
        }
        __syncthreads();

        // combine + store: 4 outputs per thread
        #pragma unroll
        for (int p = 0; p < 4; p++) {
            int idx = t + p * 512;
            int r = idx >> 8, c = idx & 255;
            float v = sm.e.pacc[ r       * 256 + c] + sm.e.pacc[( 8 + r) * 256 + c]
                    + sm.e.pacc[(16 + r) * 256 + c] + sm.e.pacc[(24 + r) * 256 + c];
            out[(r0 + r) * DD + cg * 256 + c] = v;
        }
    }
}

extern "C" void kernel_launch(void* const* d_in, const int* in_sizes, int n_in,
                              void* d_out, int out_size)
{
    const float* var  = (const float*)d_in[0];
    const float* grad = (const float*)d_in[1];
    float* out = (float*)d_out;
    stein_fused<<<NBLK, NTHR>>>(var, grad, out);
}